// round 3
// baseline (speedup 1.0000x reference)
#include <cuda_runtime.h>
#include <stdint.h>

#define NNODES 50000
#define NEDGES 800000
#define DIM    128

// ---------------- scratch (device globals; no allocation allowed) ----------
__device__ float g_h[NNODES * DIM];      // gemm output (pre-aggregation)
__device__ float g_a[NNODES * DIM];      // layer activation output
__device__ int   g_counts[NNODES];
__device__ int   g_cursor[NNODES];
__device__ int   g_rowptr[NNODES + 1];
__device__ float g_dinv[NNODES];
__device__ int   g_src[NEDGES];
__device__ float g_w[NEDGES];
__device__ int   g_is64;                 // edge_index dtype flag

// ---------------- dtype detection ------------------------------------------
// Reference declares int64 but JAX default config downcasts to int32.
// Sample 16 qword reads (in-bounds under BOTH interpretations: buffer is
// >= E qwords either way). If int32 data is read as int64, the high word is a
// random index (nonzero w.p. 49999/50000), so "all 16 in [0,N)" identifies
// true int64 with false-positive probability ~(1/50000)^16.
__global__ void detect_kernel(const long long* __restrict__ ei, int E) {
    int ok = 1;
    for (int i = 0; i < 16; i++) {
        long long v = ei[(long long)i * 7 + 1];
        if (v < 0 || v >= NNODES) ok = 0;
    }
    g_is64 = ok;
}

__device__ __forceinline__ int edge_elem(const void* ei, long long idx) {
    if (g_is64) return (int)((const long long*)ei)[idx];
    return ((const int*)ei)[idx];
}

// ---------------- graph preprocessing --------------------------------------

__global__ void zero_kernel(int n) {
    int i = blockIdx.x * blockDim.x + threadIdx.x;
    if (i < n) { g_counts[i] = 0; g_cursor[i] = 0; }
}

__global__ void count_kernel(const void* __restrict__ ei, int E) {
    int e = blockIdx.x * blockDim.x + threadIdx.x;
    if (e < E) {
        int d = edge_elem(ei, (long long)E + e);
        atomicAdd(&g_counts[d], 1);
    }
}

__global__ void dinv_kernel(int n) {
    int i = blockIdx.x * blockDim.x + threadIdx.x;
    if (i < n) g_dinv[i] = rsqrtf(1.0f + (float)g_counts[i]);
}

// single-block exclusive scan of g_counts -> g_rowptr
__global__ void scan_kernel(int n, int total) {
    __shared__ int sm[1024];
    int tid = threadIdx.x;
    int chunk = (n + 1023) / 1024;
    int start = tid * chunk;
    int s = 0;
    for (int j = 0; j < chunk; j++) {
        int idx = start + j;
        if (idx < n) s += g_counts[idx];
    }
    sm[tid] = s;
    __syncthreads();
    for (int off = 1; off < 1024; off <<= 1) {
        int v = (tid >= off) ? sm[tid - off] : 0;
        __syncthreads();
        sm[tid] += v;
        __syncthreads();
    }
    int run = sm[tid] - s;  // exclusive prefix of this chunk
    for (int j = 0; j < chunk; j++) {
        int idx = start + j;
        if (idx < n) {
            g_rowptr[idx] = run;
            run += g_counts[idx];
        }
    }
    if (tid == 0) g_rowptr[n] = total;
}

__global__ void fill_kernel(const void* __restrict__ ei, int E) {
    int e = blockIdx.x * blockDim.x + threadIdx.x;
    if (e < E) {
        int s = edge_elem(ei, e);
        int d = edge_elem(ei, (long long)E + e);
        int p = g_rowptr[d] + atomicAdd(&g_cursor[d], 1);
        g_src[p] = s;
        g_w[p]   = g_dinv[s] * g_dinv[d];
    }
}

// ---------------- GEMM: O[n,HOUT] = X[n,128] @ W[128,HOUT] ------------------
// Persistent grid; warp-per-row; W resident in shared; LDS.128 W reads.

template <int HOUT>
__global__ __launch_bounds__(256) void gemm_kernel(
    const float* __restrict__ X, const float* __restrict__ W,
    float* __restrict__ O, int n)
{
    extern __shared__ float Ws[];
    for (int i = threadIdx.x; i < DIM * HOUT / 4; i += blockDim.x)
        ((float4*)Ws)[i] = ((const float4*)W)[i];
    __syncthreads();

    constexpr int V = HOUT / 32;           // 4 or 2 floats per lane
    int lane = threadIdx.x & 31;
    int gw   = (blockIdx.x * blockDim.x + threadIdx.x) >> 5;
    int nw   = (gridDim.x * blockDim.x) >> 5;

    for (int row = gw; row < n; row += nw) {
        const float4* xr = (const float4*)(X + (size_t)row * DIM);
        float acc[V];
#pragma unroll
        for (int v = 0; v < V; v++) acc[v] = 0.f;

#pragma unroll
        for (int k4 = 0; k4 < DIM / 4; k4++) {
            float4 xv = __ldg(&xr[k4]);
#pragma unroll
            for (int j = 0; j < 4; j++) {
                float xk = (j == 0) ? xv.x : (j == 1) ? xv.y : (j == 2) ? xv.z : xv.w;
                if constexpr (V == 4) {
                    float4 wv = ((const float4*)&Ws[(k4 * 4 + j) * HOUT])[lane];
                    acc[0] += xk * wv.x; acc[1] += xk * wv.y;
                    acc[2] += xk * wv.z; acc[3] += xk * wv.w;
                } else {
                    float2 wv = ((const float2*)&Ws[(k4 * 4 + j) * HOUT])[lane];
                    acc[0] += xk * wv.x; acc[1] += xk * wv.y;
                }
            }
        }
        float* o = O + (size_t)row * HOUT + lane * V;
#pragma unroll
        for (int v = 0; v < V; v++) o[v] = acc[v];
    }
}

// ---------------- aggregation: out[i] = sum_e w_e*h[src_e] + dinv2*h[i] + b -
// warp-per-node CSR gather, no atomics, edge loop unrolled x4 for MLP.

template <int HOUT, bool RELU>
__global__ __launch_bounds__(256) void agg_kernel(
    const float* __restrict__ Hm, const float* __restrict__ bias,
    float* __restrict__ O, int n)
{
    constexpr int V = HOUT / 32;
    int lane = threadIdx.x & 31;
    int gw   = (blockIdx.x * blockDim.x + threadIdx.x) >> 5;
    int nw   = (gridDim.x * blockDim.x) >> 5;

    float bv[V];
#pragma unroll
    for (int v = 0; v < V; v++) bv[v] = bias[lane * V + v];

    for (int node = gw; node < n; node += nw) {
        float di = g_dinv[node];
        float sw = di * di;
        float acc[V];

        const float* hn = Hm + (size_t)node * HOUT + lane * V;
        if constexpr (V == 4) {
            float4 t = *reinterpret_cast<const float4*>(hn);
            acc[0] = sw * t.x; acc[1] = sw * t.y; acc[2] = sw * t.z; acc[3] = sw * t.w;
        } else {
            float2 t = *reinterpret_cast<const float2*>(hn);
            acc[0] = sw * t.x; acc[1] = sw * t.y;
        }

        int p = g_rowptr[node];
        int e = g_rowptr[node + 1];

        for (; p + 4 <= e; p += 4) {
            int   s0 = g_src[p],   s1 = g_src[p+1], s2 = g_src[p+2], s3 = g_src[p+3];
            float w0 = g_w[p],     w1 = g_w[p+1],   w2 = g_w[p+2],   w3 = g_w[p+3];
            const float* h0 = Hm + (size_t)s0 * HOUT + lane * V;
            const float* h1 = Hm + (size_t)s1 * HOUT + lane * V;
            const float* h2 = Hm + (size_t)s2 * HOUT + lane * V;
            const float* h3 = Hm + (size_t)s3 * HOUT + lane * V;
            if constexpr (V == 4) {
                float4 a0 = *reinterpret_cast<const float4*>(h0);
                float4 a1 = *reinterpret_cast<const float4*>(h1);
                float4 a2 = *reinterpret_cast<const float4*>(h2);
                float4 a3 = *reinterpret_cast<const float4*>(h3);
                acc[0] += w0*a0.x; acc[1] += w0*a0.y; acc[2] += w0*a0.z; acc[3] += w0*a0.w;
                acc[0] += w1*a1.x; acc[1] += w1*a1.y; acc[2] += w1*a1.z; acc[3] += w1*a1.w;
                acc[0] += w2*a2.x; acc[1] += w2*a2.y; acc[2] += w2*a2.z; acc[3] += w2*a2.w;
                acc[0] += w3*a3.x; acc[1] += w3*a3.y; acc[2] += w3*a3.z; acc[3] += w3*a3.w;
            } else {
                float2 a0 = *reinterpret_cast<const float2*>(h0);
                float2 a1 = *reinterpret_cast<const float2*>(h1);
                float2 a2 = *reinterpret_cast<const float2*>(h2);
                float2 a3 = *reinterpret_cast<const float2*>(h3);
                acc[0] += w0*a0.x; acc[1] += w0*a0.y;
                acc[0] += w1*a1.x; acc[1] += w1*a1.y;
                acc[0] += w2*a2.x; acc[1] += w2*a2.y;
                acc[0] += w3*a3.x; acc[1] += w3*a3.y;
            }
        }
        for (; p < e; p++) {
            int   s0 = g_src[p];
            float w0 = g_w[p];
            const float* h0 = Hm + (size_t)s0 * HOUT + lane * V;
            if constexpr (V == 4) {
                float4 a0 = *reinterpret_cast<const float4*>(h0);
                acc[0] += w0*a0.x; acc[1] += w0*a0.y; acc[2] += w0*a0.z; acc[3] += w0*a0.w;
            } else {
                float2 a0 = *reinterpret_cast<const float2*>(h0);
                acc[0] += w0*a0.x; acc[1] += w0*a0.y;
            }
        }

        float* o = O + (size_t)node * HOUT + lane * V;
#pragma unroll
        for (int v = 0; v < V; v++) {
            float r = acc[v] + bv[v];
            if (RELU) r = fmaxf(r, 0.f);
            o[v] = r;
        }
    }
}

// ---------------- launch ----------------------------------------------------

extern "C" void kernel_launch(void* const* d_in, const int* in_sizes, int n_in,
                              void* d_out, int out_size)
{
    const float* x  = (const float*)d_in[0];
    const void*  ei = d_in[1];
    const float* W1 = (const float*)d_in[2];
    const float* b1 = (const float*)d_in[3];
    const float* W2 = (const float*)d_in[4];
    const float* b2 = (const float*)d_in[5];
    const float* W3 = (const float*)d_in[6];
    const float* b3 = (const float*)d_in[7];
    float* out = (float*)d_out;

    int n = in_sizes[0] / DIM;
    int E = in_sizes[1] / 2;

    float* h_ptr; float* a_ptr;
    cudaGetSymbolAddress((void**)&h_ptr, g_h);
    cudaGetSymbolAddress((void**)&a_ptr, g_a);

    cudaFuncSetAttribute((const void*)gemm_kernel<128>,
                         cudaFuncAttributeMaxDynamicSharedMemorySize, DIM * 128 * 4);
    cudaFuncSetAttribute((const void*)gemm_kernel<64>,
                         cudaFuncAttributeMaxDynamicSharedMemorySize, DIM * 64 * 4);

    const int TB = 256;
    // --- dtype detection + CSR build (once per call) ---
    detect_kernel<<<1, 1>>>((const long long*)ei, E);
    zero_kernel <<<(n + TB - 1) / TB, TB>>>(n);
    count_kernel<<<(E + TB - 1) / TB, TB>>>(ei, E);
    dinv_kernel <<<(n + TB - 1) / TB, TB>>>(n);
    scan_kernel <<<1, 1024>>>(n, E);
    fill_kernel <<<(E + TB - 1) / TB, TB>>>(ei, E);

    // persistent GEMM grid: 3 blocks/SM x ~148 SMs (64KB smem each)
    const int GEMM_BLOCKS = 444;
    int rb = (n + 7) / 8;   // agg: warp-per-node, 8 warps/block

    // layer 1: x -> g_h -> g_a (relu)
    gemm_kernel<128><<<GEMM_BLOCKS, TB, DIM * 128 * 4>>>(x, W1, h_ptr, n);
    agg_kernel<128, true><<<rb, TB>>>(h_ptr, b1, a_ptr, n);

    // layer 2: g_a -> g_h -> g_a (relu)
    gemm_kernel<128><<<GEMM_BLOCKS, TB, DIM * 128 * 4>>>(a_ptr, W2, h_ptr, n);
    agg_kernel<128, true><<<rb, TB>>>(h_ptr, b2, a_ptr, n);

    // layer 3: g_a -> g_h (64 wide) -> d_out (no relu)
    gemm_kernel<64><<<GEMM_BLOCKS, TB, DIM * 64 * 4>>>(a_ptr, W3, h_ptr, n);
    agg_kernel<64, false><<<rb, TB>>>(h_ptr, b3, out, n);
}

// round 4
// speedup vs baseline: 1.5167x; 1.5167x over previous
#include <cuda_runtime.h>
#include <stdint.h>

#define NNODES 50000
#define NEDGES 800000
#define DIM    128

// ---------------- scratch (device globals; no allocation allowed) ----------
__device__ float g_h[NNODES * DIM];      // gemm output (pre-aggregation)
__device__ float g_a[NNODES * DIM];      // layer activation output
__device__ int   g_counts[NNODES];
__device__ int   g_cursor[NNODES];
__device__ int   g_rowptr[NNODES + 1];
__device__ float g_dinv[NNODES];
__device__ int2  g_edge[NEDGES];         // {src, w bits}
__device__ int   g_is64;                 // edge_index dtype flag

// ---------------- dtype detection ------------------------------------------
// Reference declares int64 but JAX default config downcasts to int32.
__global__ void detect_kernel(const long long* __restrict__ ei, int E) {
    int ok = 1;
    for (int i = 0; i < 16; i++) {
        long long v = ei[(long long)i * 7 + 1];
        if (v < 0 || v >= NNODES) ok = 0;
    }
    g_is64 = ok;
}

__device__ __forceinline__ int edge_elem(const void* ei, long long idx) {
    if (g_is64) return (int)((const long long*)ei)[idx];
    return ((const int*)ei)[idx];
}

// ---------------- graph preprocessing --------------------------------------

__global__ void zero_kernel(int n) {
    int i = blockIdx.x * blockDim.x + threadIdx.x;
    if (i < n) { g_counts[i] = 0; g_cursor[i] = 0; }
}

__global__ void count_kernel(const void* __restrict__ ei, int E) {
    int e = blockIdx.x * blockDim.x + threadIdx.x;
    if (e < E) {
        int d = edge_elem(ei, (long long)E + e);
        atomicAdd(&g_counts[d], 1);
    }
}

__global__ void dinv_kernel(int n) {
    int i = blockIdx.x * blockDim.x + threadIdx.x;
    if (i < n) g_dinv[i] = rsqrtf(1.0f + (float)g_counts[i]);
}

// single-block exclusive scan of g_counts -> g_rowptr
__global__ void scan_kernel(int n, int total) {
    __shared__ int sm[1024];
    int tid = threadIdx.x;
    int chunk = (n + 1023) / 1024;
    int start = tid * chunk;
    int s = 0;
    for (int j = 0; j < chunk; j++) {
        int idx = start + j;
        if (idx < n) s += g_counts[idx];
    }
    sm[tid] = s;
    __syncthreads();
    for (int off = 1; off < 1024; off <<= 1) {
        int v = (tid >= off) ? sm[tid - off] : 0;
        __syncthreads();
        sm[tid] += v;
        __syncthreads();
    }
    int run = sm[tid] - s;
    for (int j = 0; j < chunk; j++) {
        int idx = start + j;
        if (idx < n) {
            g_rowptr[idx] = run;
            run += g_counts[idx];
        }
    }
    if (tid == 0) g_rowptr[n] = total;
}

__global__ void fill_kernel(const void* __restrict__ ei, int E) {
    int e = blockIdx.x * blockDim.x + threadIdx.x;
    if (e < E) {
        int s = edge_elem(ei, e);
        int d = edge_elem(ei, (long long)E + e);
        int p = g_rowptr[d] + atomicAdd(&g_cursor[d], 1);
        g_edge[p] = make_int2(s, __float_as_int(g_dinv[s] * g_dinv[d]));
    }
}

// ---------------- GEMM: O[n,HOUT] = X[n,128] @ W[128,HOUT] ------------------
// Persistent grid; 4 rows per warp (each LDS.128 of W feeds 16 warp-FFMAs →
// smem demand 64 B/cyc/SM, below the 128 B/cyc crossbar → FFMA-issue-bound).

template <int HOUT>
__global__ __launch_bounds__(256) void gemm_kernel(
    const float* __restrict__ X, const float* __restrict__ W,
    float* __restrict__ O, int n)
{
    extern __shared__ float Ws[];
    for (int i = threadIdx.x; i < DIM * HOUT / 4; i += blockDim.x)
        ((float4*)Ws)[i] = ((const float4*)W)[i];
    __syncthreads();

    constexpr int V = HOUT / 32;   // floats per lane (4 or 2)
    constexpr int R = 4;           // rows per warp
    int lane = threadIdx.x & 31;
    int gw   = (blockIdx.x * blockDim.x + threadIdx.x) >> 5;
    int nw   = (gridDim.x * blockDim.x) >> 5;
    int ngroups = (n + R - 1) / R;

    for (int grp = gw; grp < ngroups; grp += nw) {
        int row0 = grp * R;
        const float4* xr[R];
#pragma unroll
        for (int r = 0; r < R; r++) {
            int rr = row0 + r; if (rr > n - 1) rr = n - 1;   // clamp (n%4==0 normally)
            xr[r] = (const float4*)(X + (size_t)rr * DIM);
        }
        float acc[R][V];
#pragma unroll
        for (int r = 0; r < R; r++)
#pragma unroll
            for (int v = 0; v < V; v++) acc[r][v] = 0.f;

#pragma unroll
        for (int k4 = 0; k4 < DIM / 4; k4++) {
            float4 xv[R];
#pragma unroll
            for (int r = 0; r < R; r++) xv[r] = __ldg(&xr[r][k4]);
#pragma unroll
            for (int j = 0; j < 4; j++) {
                if constexpr (V == 4) {
                    float4 wv = ((const float4*)&Ws[(k4 * 4 + j) * HOUT])[lane];
#pragma unroll
                    for (int r = 0; r < R; r++) {
                        float xk = (j == 0) ? xv[r].x : (j == 1) ? xv[r].y
                                 : (j == 2) ? xv[r].z : xv[r].w;
                        acc[r][0] += xk * wv.x; acc[r][1] += xk * wv.y;
                        acc[r][2] += xk * wv.z; acc[r][3] += xk * wv.w;
                    }
                } else {
                    float2 wv = ((const float2*)&Ws[(k4 * 4 + j) * HOUT])[lane];
#pragma unroll
                    for (int r = 0; r < R; r++) {
                        float xk = (j == 0) ? xv[r].x : (j == 1) ? xv[r].y
                                 : (j == 2) ? xv[r].z : xv[r].w;
                        acc[r][0] += xk * wv.x; acc[r][1] += xk * wv.y;
                    }
                }
            }
        }
#pragma unroll
        for (int r = 0; r < R; r++) {
            int rr = row0 + r;
            if (rr < n) {
                float* o = O + (size_t)rr * HOUT + lane * V;
                if constexpr (V == 4)
                    *(float4*)o = make_float4(acc[r][0], acc[r][1], acc[r][2], acc[r][3]);
                else
                    *(float2*)o = make_float2(acc[r][0], acc[r][1]);
            }
        }
    }
}

// ---------------- aggregation: out[i] = sum_e w_e*h[src_e] + dinv2*h[i] + b -
// warp-per-node CSR gather; edge loop unrolled x8 (MLP=8 float4 loads/lane).

template <int HOUT, bool RELU>
__global__ __launch_bounds__(256) void agg_kernel(
    const float* __restrict__ Hm, const float* __restrict__ bias,
    float* __restrict__ O, int n)
{
    constexpr int V = HOUT / 32;
    int lane = threadIdx.x & 31;
    int gw   = (blockIdx.x * blockDim.x + threadIdx.x) >> 5;
    int nw   = (gridDim.x * blockDim.x) >> 5;

    float bv[V];
#pragma unroll
    for (int v = 0; v < V; v++) bv[v] = bias[lane * V + v];

    for (int node = gw; node < n; node += nw) {
        float di = g_dinv[node];
        float sw = di * di;
        float acc[V];

        const float* hn = Hm + (size_t)node * HOUT + lane * V;
        if constexpr (V == 4) {
            float4 t = *reinterpret_cast<const float4*>(hn);
            acc[0] = sw * t.x; acc[1] = sw * t.y; acc[2] = sw * t.z; acc[3] = sw * t.w;
        } else {
            float2 t = *reinterpret_cast<const float2*>(hn);
            acc[0] = sw * t.x; acc[1] = sw * t.y;
        }

        int p = g_rowptr[node];
        int e = g_rowptr[node + 1];

        for (; p + 8 <= e; p += 8) {
            int2  ed[8];
#pragma unroll
            for (int u = 0; u < 8; u++) ed[u] = g_edge[p + u];
            if constexpr (V == 4) {
                float4 a[8];
#pragma unroll
                for (int u = 0; u < 8; u++)
                    a[u] = *reinterpret_cast<const float4*>(
                        Hm + (size_t)ed[u].x * HOUT + lane * 4);
#pragma unroll
                for (int u = 0; u < 8; u++) {
                    float w = __int_as_float(ed[u].y);
                    acc[0] += w * a[u].x; acc[1] += w * a[u].y;
                    acc[2] += w * a[u].z; acc[3] += w * a[u].w;
                }
            } else {
                float2 a[8];
#pragma unroll
                for (int u = 0; u < 8; u++)
                    a[u] = *reinterpret_cast<const float2*>(
                        Hm + (size_t)ed[u].x * HOUT + lane * 2);
#pragma unroll
                for (int u = 0; u < 8; u++) {
                    float w = __int_as_float(ed[u].y);
                    acc[0] += w * a[u].x; acc[1] += w * a[u].y;
                }
            }
        }
        for (; p < e; p++) {
            int2 ed = g_edge[p];
            float w = __int_as_float(ed.y);
            const float* h0 = Hm + (size_t)ed.x * HOUT + lane * V;
            if constexpr (V == 4) {
                float4 a0 = *reinterpret_cast<const float4*>(h0);
                acc[0] += w*a0.x; acc[1] += w*a0.y; acc[2] += w*a0.z; acc[3] += w*a0.w;
            } else {
                float2 a0 = *reinterpret_cast<const float2*>(h0);
                acc[0] += w*a0.x; acc[1] += w*a0.y;
            }
        }

        float* o = O + (size_t)node * HOUT + lane * V;
#pragma unroll
        for (int v = 0; v < V; v++) {
            float r = acc[v] + bv[v];
            if (RELU) r = fmaxf(r, 0.f);
            o[v] = r;
        }
    }
}

// ---------------- launch ----------------------------------------------------

extern "C" void kernel_launch(void* const* d_in, const int* in_sizes, int n_in,
                              void* d_out, int out_size)
{
    const float* x  = (const float*)d_in[0];
    const void*  ei = d_in[1];
    const float* W1 = (const float*)d_in[2];
    const float* b1 = (const float*)d_in[3];
    const float* W2 = (const float*)d_in[4];
    const float* b2 = (const float*)d_in[5];
    const float* W3 = (const float*)d_in[6];
    const float* b3 = (const float*)d_in[7];
    float* out = (float*)d_out;

    int n = in_sizes[0] / DIM;
    int E = in_sizes[1] / 2;

    float* h_ptr; float* a_ptr;
    cudaGetSymbolAddress((void**)&h_ptr, g_h);
    cudaGetSymbolAddress((void**)&a_ptr, g_a);

    cudaFuncSetAttribute((const void*)gemm_kernel<128>,
                         cudaFuncAttributeMaxDynamicSharedMemorySize, DIM * 128 * 4);
    cudaFuncSetAttribute((const void*)gemm_kernel<64>,
                         cudaFuncAttributeMaxDynamicSharedMemorySize, DIM * 64 * 4);

    const int TB = 256;
    // --- dtype detection + CSR build (once per call) ---
    detect_kernel<<<1, 1>>>((const long long*)ei, E);
    zero_kernel <<<(n + TB - 1) / TB, TB>>>(n);
    count_kernel<<<(E + TB - 1) / TB, TB>>>(ei, E);
    dinv_kernel <<<(n + TB - 1) / TB, TB>>>(n);
    scan_kernel <<<1, 1024>>>(n, E);
    fill_kernel <<<(E + TB - 1) / TB, TB>>>(ei, E);

    // persistent GEMM grid: 3 blocks/SM x ~148 SMs (64KB smem each)
    const int GEMM_BLOCKS = 444;
    int rb = (n + 7) / 8;   // agg: warp-per-node, 8 warps/block

    // layer 1: x -> g_h -> g_a (relu)
    gemm_kernel<128><<<GEMM_BLOCKS, TB, DIM * 128 * 4>>>(x, W1, h_ptr, n);
    agg_kernel<128, true><<<rb, TB>>>(h_ptr, b1, a_ptr, n);

    // layer 2: g_a -> g_h -> g_a (relu)
    gemm_kernel<128><<<GEMM_BLOCKS, TB, DIM * 128 * 4>>>(a_ptr, W2, h_ptr, n);
    agg_kernel<128, true><<<rb, TB>>>(h_ptr, b2, a_ptr, n);

    // layer 3: g_a -> g_h (64 wide) -> d_out (no relu)
    gemm_kernel<64><<<GEMM_BLOCKS, TB, DIM * 64 * 4>>>(a_ptr, W3, h_ptr, n);
    agg_kernel<64, false><<<rb, TB>>>(h_ptr, b3, out, n);
}